// round 10
// baseline (speedup 1.0000x reference)
#include <cuda_runtime.h>
#include <math.h>
#include <stdint.h>

#define BATCH   8
#define CIN     64
#define COUT    64
#define NCO     256
#define T_LEN   16384
#define CHUNK   16
#define NCH     (T_LEN / CHUNK)      // 1024

// ---------------- scratch (device globals: no cudaMalloc allowed) ----------
__device__ float  g_u[(size_t)BATCH * NCO * T_LEN];   // v_local[b][n][t]
__device__ float2 g_lam[NCO];                         // lambda
__device__ float2 g_lamL[NCO];                        // lambda^16   (dbl-accurate)
__device__ float2 g_lamL32[NCO];                      // lambda^512  (dbl-accurate)
__device__ float2 g_lpow[NCO * CHUNK];                // lambda^(k+1), k=0..15
__device__ float  g_bh2[CIN * NCO * 2];               // B_hat dup pairs [c][n](w,w)
__device__ float  g_ct2[NCO * COUT * 2];              // C dup pairs [n][d](w,w)
__device__ float2 g_zend[(size_t)BATCH * NCO * NCH];
__device__ float2 g_zstart[(size_t)BATCH * NCO * NCH];

// ---------------- packed fp32x2 helpers (sm_100+) --------------------------
__device__ __forceinline__ void fma2(unsigned long long& acc,
                                     unsigned long long a, unsigned long long b) {
    asm("fma.rn.f32x2 %0, %1, %2, %0;" : "+l"(acc) : "l"(a), "l"(b));
}
__device__ __forceinline__ void cp16(uint32_t s, const float* g) {
    asm volatile("cp.async.cg.shared.global [%0], [%1], 16;\n"
                 :: "r"(s), "l"(g) : "memory");
}
__device__ __forceinline__ uint32_t smem_u32(const void* p) {
    uint32_t r;
    asm("{ .reg .u64 t0_; cvta.to.shared.u64 t0_, %1; cvt.u32.u64 %0, t0_; }"
        : "=r"(r) : "l"(p));
    return r;
}

// ---------------- kernel P: per-coefficient precompute ---------------------
__global__ void kP(const float* __restrict__ A, const float* __restrict__ Bm,
                   const float* __restrict__ log_dt, const float* __restrict__ Cm) {
    int n = threadIdx.x;              // 256 threads, one per coeff
    double la = (double)A[2 * n];
    double ai = (double)A[2 * n + 1];
    double dt = exp((double)log_dt[n]);
    double sp = log1p(exp(la));       // softplus
    double re = -dt * sp;
    double im =  dt * ai;
    double er = exp(re);
    g_lam[n]  = make_float2((float)(er * cos(im)), (float)(er * sin(im)));
    double erL = exp(re * (double)CHUNK);
    double imL = im * (double)CHUNK;
    g_lamL[n] = make_float2((float)(erL * cos(imL)), (float)(erL * sin(imL)));
    double er32 = exp(re * (double)(CHUNK * 32));
    double im32 = im * (double)(CHUNK * 32);
    g_lamL32[n] = make_float2((float)(er32 * cos(im32)), (float)(er32 * sin(im32)));
    for (int k = 0; k < CHUNK; k++) {             // lambda^(k+1), dbl-accurate
        double ek = exp(re * (double)(k + 1));
        double ik = im * (double)(k + 1);
        g_lpow[n * CHUNK + k] =
            make_float2((float)(ek * cos(ik)), (float)(ek * sin(ik)));
    }
    float dtf = (float)dt;
    for (int c = 0; c < CIN; c++) {
        float w = Bm[n * CIN + c] * dtf;
        g_bh2[(c * NCO + n) * 2 + 0] = w;
        g_bh2[(c * NCO + n) * 2 + 1] = w;
    }
    for (int d = 0; d < COUT; d++) {
        float w = Cm[d * NCO + n];
        g_ct2[(n * COUT + d) * 2 + 0] = w;
        g_ct2[(n * COUT + d) * 2 + 1] = w;
    }
}

// ---------------- kernel A: v_local = scan(B_hat @ x) ----------------------
// CTA = (t-macro-tile 256, b), 256 threads, 4 sub-tiles of 64t, double-
// buffered cp.async x panels. Thread = 4n x 16t register tile.
#define SUB_A  64
#define NSUB   4
#define XSP    68
#define XPANE  (CIN * XSP)                    // floats per x panel

__global__ void __launch_bounds__(256, 2) kA(const float* __restrict__ x) {
    __shared__ float xs[2 * XPANE];           // 34.8 KB
    int b = blockIdx.y, mt = blockIdx.x;
    int tid = threadIdx.x;
    size_t tbase = (size_t)mt * (SUB_A * NSUB);
    uint32_t sbase = smem_u32(xs);

    // prefetch sub-tile 0 into buffer 0 (64c x 64t = 1024 float4)
    for (int i = tid; i < CIN * 16; i += 256) {
        int c = i >> 4, q = i & 15;
        cp16(sbase + (uint32_t)(c * XSP + 4 * q) * 4,
             &x[((size_t)(b * CIN + c)) * T_LEN + tbase + 4 * q]);
    }
    asm volatile("cp.async.commit_group;\n" ::: "memory");

    int n0   = (tid >> 2) * 4;
    int tg   = tid & 3;
    int toff = tg * 16;

    for (int s = 0; s < NSUB; s++) {
        float* cur = xs + (s & 1) * XPANE;
        asm volatile("cp.async.wait_group 0;\n" ::: "memory");
        __syncthreads();

        // prefetch next sub-tile into the other buffer; overlaps GEMM below
        if (s < NSUB - 1) {
            uint32_t nb = (uint32_t)(((s + 1) & 1) * XPANE) * 4;
            for (int i = tid; i < CIN * 16; i += 256) {
                int c = i >> 4, q = i & 15;
                cp16(sbase + nb + (uint32_t)(c * XSP + 4 * q) * 4,
                     &x[((size_t)(b * CIN + c)) * T_LEN + tbase + (s + 1) * SUB_A + 4 * q]);
            }
            asm volatile("cp.async.commit_group;\n" ::: "memory");
        }

        unsigned long long acc2[4][8];        // 4 n x 16 t
#pragma unroll
        for (int r = 0; r < 4; r++)
#pragma unroll
            for (int j = 0; j < 8; j++) acc2[r][j] = 0ULL;

        for (int c = 0; c < CIN; c++) {
            const ulonglong2* wv =
                (const ulonglong2*)&g_bh2[(c * NCO + n0) * 2];  // dup pairs
            ulonglong2 w01 = wv[0], w23 = wv[1];
            unsigned long long w[4] = {w01.x, w01.y, w23.x, w23.y};
            const ulonglong2* xv = (const ulonglong2*)&cur[c * XSP + toff];
            ulonglong2 va = xv[0], vb = xv[1], vc = xv[2], vd = xv[3];
            unsigned long long v[8] = {va.x, va.y, vb.x, vb.y,
                                       vc.x, vc.y, vd.x, vd.y};
#pragma unroll
            for (int r = 0; r < 4; r++)
#pragma unroll
                for (int j = 0; j < 8; j++)
                    fma2(acc2[r][j], w[r], v[j]);
        }

        // pass-1: 16-step chunk-local recurrence, zero init; store v_local
        size_t t0 = tbase + (size_t)s * SUB_A;
        int chunk = mt * 16 + s * 4 + tg;
#pragma unroll
        for (int r = 0; r < 4; r++) {
            int n = n0 + r;
            float2 lam = g_lam[n];
            float vl[16];
            float zr = 0.f, zi = 0.f;
#pragma unroll
            for (int j = 0; j < 8; j++) {
                float2 u2 = *(float2*)&acc2[r][j];
                float nr = fmaf(lam.x, zr, fmaf(-lam.y, zi, u2.x));
                float ni = fmaf(lam.x, zi, lam.y * zr);
                zr = nr; zi = ni; vl[2 * j] = zr;
                nr = fmaf(lam.x, zr, fmaf(-lam.y, zi, u2.y));
                ni = fmaf(lam.x, zi, lam.y * zr);
                zr = nr; zi = ni; vl[2 * j + 1] = zr;
            }
            g_zend[((size_t)(b * NCO + n)) * NCH + chunk] = make_float2(zr, zi);

            float* orow = &g_u[((size_t)(b * NCO + n)) * T_LEN + t0 + toff];
#pragma unroll
            for (int q = 0; q < 4; q++)
                *(float4*)&orow[4 * q] =
                    make_float4(vl[4 * q], vl[4 * q + 1],
                                vl[4 * q + 2], vl[4 * q + 3]);
        }
    }
}

// ---------------- kernel B: cross-chunk scan, warp-parallel ----------------
// One warp per chain (2048 chains). Lane owns 32 contiguous chunk states:
// local total -> Kogge-Stone scan of affine maps (a,b) -> replay + write.
__global__ void __launch_bounds__(256) kB() {
    int warp = (blockIdx.x << 3) + (threadIdx.x >> 5);  // chain = b*256+n
    int lane = threadIdx.x & 31;
    int n = warp & 255;
    float2 lamL  = g_lamL[n];
    float2 lam32 = g_lamL32[n];
    size_t base = (size_t)warp * NCH + (size_t)lane * 32;

    float2 z[32];
#pragma unroll
    for (int i = 0; i < 32; i++) z[i] = g_zend[base + i];

    // segment total: state after 32 steps with zero init (complex input)
    float tr = 0.f, ti = 0.f;
#pragma unroll
    for (int i = 0; i < 32; i++) {
        float nr = fmaf(lamL.x, tr, fmaf(-lamL.y, ti, z[i].x));
        float ni = fmaf(lamL.x, ti, fmaf( lamL.y, tr, z[i].y));
        tr = nr; ti = ni;
    }

    // KS inclusive scan of affine maps f(s) = a*s + b, a = lamL^32 = lam32
    float ar = lam32.x, ai = lam32.y, br = tr, bi = ti;
#pragma unroll
    for (int d = 1; d < 32; d <<= 1) {
        float par = __shfl_up_sync(0xffffffffu, ar, d);
        float pai = __shfl_up_sync(0xffffffffu, ai, d);
        float pbr = __shfl_up_sync(0xffffffffu, br, d);
        float pbi = __shfl_up_sync(0xffffffffu, bi, d);
        if (lane >= d) {
            float nbr = fmaf(ar, pbr, fmaf(-ai, pbi, br));   // b = a*pb + b
            float nbi = fmaf(ar, pbi, fmaf( ai, pbr, bi));
            float nar = fmaf(ar, par, -ai * pai);            // a = a*pa
            float nai = fmaf(ar, pai,  ai * par);
            br = nbr; bi = nbi; ar = nar; ai = nai;
        }
    }
    // state entering this lane's segment = inclusive result of lane-1
    float er = __shfl_up_sync(0xffffffffu, br, 1);
    float ei = __shfl_up_sync(0xffffffffu, bi, 1);
    if (lane == 0) { er = 0.f; ei = 0.f; }

    // replay segment, writing the state entering each chunk
    float gr = er, gi = ei;
#pragma unroll
    for (int i = 0; i < 32; i++) {
        g_zstart[base + i] = make_float2(gr, gi);
        float nr = fmaf(lamL.x, gr, fmaf(-lamL.y, gi, z[i].x));
        float ni = fmaf(lamL.x, gi, fmaf( lamL.y, gr, z[i].y));
        gr = nr; gi = ni;
    }
}

// ---------------- kernel C: parallel correction + y = C @ v ----------------
// CTA = (t-tile of 256, b), 256 threads. 8 n-panels of 32, double-buffered
// cp.async. Thread = 4d x 16t: d0 = (tid&15)*4, tg = tid>>4.
#define TILE_C 256
#define NPC    32
#define UPP    260
#define PANE   (NPC * UPP)                    // floats per panel buffer
#define SMEM_C (2 * PANE * 4)                 // 66.6 KB

extern __shared__ float s_dyn[];

__global__ void __launch_bounds__(256, 2) kC(float* __restrict__ out) {
    int b = blockIdx.y, tile = blockIdx.x;
    int tid = threadIdx.x;
    size_t t0 = (size_t)tile * TILE_C;
    uint32_t sbase = smem_u32(s_dyn);

    int d0   = (tid & 15) * 4;
    int tgof = (tid >> 4) * 16;

    unsigned long long acc2[4][8];            // 4 d x 16 t
#pragma unroll
    for (int r = 0; r < 4; r++)
#pragma unroll
        for (int i = 0; i < 8; i++) acc2[r][i] = 0ULL;

    // prefetch panel 0 into buffer 0
    for (int i = tid; i < NPC * 64; i += 256) {
        int np = i >> 6, q = i & 63;
        cp16(sbase + (uint32_t)(np * UPP + 4 * q) * 4,
             &g_u[((size_t)(b * NCO + np)) * T_LEN + t0 + 4 * q]);
    }
    asm volatile("cp.async.commit_group;\n" ::: "memory");

    for (int p = 0; p < 8; p++) {
        float* cur = s_dyn + (p & 1) * PANE;
        asm volatile("cp.async.wait_group 0;\n" ::: "memory");
        __syncthreads();

        // correction: v = v_local + Re(lambda^(k+1) * zstart)  -- PARALLEL,
        // no serial chain. 512 slots (32 n x 16 chunks), 2 per thread.
        for (int s = tid; s < NPC * 16; s += 256) {
            int n = s >> 4, c16 = s & 15;
            float2 zs = g_zstart[((size_t)(b * NCO + p * NPC + n)) * NCH
                                 + tile * 16 + c16];
            const float2* lp = &g_lpow[(p * NPC + n) * CHUNK];  // L1-hot bcast
            float* row = &cur[n * UPP + c16 * 16];
#pragma unroll
            for (int q = 0; q < 4; q++) {
                float4 uv = *(float4*)&row[4 * q];
                float2 l0 = lp[4 * q + 0], l1 = lp[4 * q + 1];
                float2 l2 = lp[4 * q + 2], l3 = lp[4 * q + 3];
                uv.x = fmaf(l0.x, zs.x, fmaf(-l0.y, zs.y, uv.x));
                uv.y = fmaf(l1.x, zs.x, fmaf(-l1.y, zs.y, uv.y));
                uv.z = fmaf(l2.x, zs.x, fmaf(-l2.y, zs.y, uv.z));
                uv.w = fmaf(l3.x, zs.x, fmaf(-l3.y, zs.y, uv.w));
                *(float4*)&row[4 * q] = uv;
            }
        }
        __syncthreads();

        // kick off next panel's async load; overlaps the GEMM below
        if (p < 7) {
            uint32_t nb = (uint32_t)(((p + 1) & 1) * PANE) * 4;
            for (int i = tid; i < NPC * 64; i += 256) {
                int np = i >> 6, q = i & 63;
                cp16(sbase + nb + (uint32_t)(np * UPP + 4 * q) * 4,
                     &g_u[((size_t)(b * NCO + (p + 1) * NPC + np)) * T_LEN + t0 + 4 * q]);
            }
            asm volatile("cp.async.commit_group;\n" ::: "memory");
        }

        // GEMM: acc[d][t] += ct[n][d] * v[n][t]  (dup-pair weights, no movs)
        for (int nn = 0; nn < NPC; nn++) {
            const ulonglong2* wv =
                (const ulonglong2*)&g_ct2[((p * NPC + nn) * COUT + d0) * 2];
            ulonglong2 w01 = wv[0], w23 = wv[1];
            unsigned long long w[4] = {w01.x, w01.y, w23.x, w23.y};
            const ulonglong2* vv = (const ulonglong2*)&cur[nn * UPP + tgof];
            ulonglong2 v0 = vv[0], v1 = vv[1], v2 = vv[2], v3 = vv[3];
            unsigned long long v[8] = {v0.x, v0.y, v1.x, v1.y, v2.x, v2.y, v3.x, v3.y};
#pragma unroll
            for (int r = 0; r < 4; r++)
#pragma unroll
                for (int j = 0; j < 8; j++)
                    fma2(acc2[r][j], w[r], v[j]);
        }
        __syncthreads();
    }

    // write y: 4 rows of 16 consecutive floats each
#pragma unroll
    for (int r = 0; r < 4; r++) {
        float* orow = &out[((size_t)(b * COUT + d0 + r)) * T_LEN + t0 + tgof];
#pragma unroll
        for (int q = 0; q < 4; q++)
            *(ulonglong2*)&orow[4 * q] =
                make_ulonglong2(acc2[r][2 * q], acc2[r][2 * q + 1]);
    }
}

// ---------------- launch ----------------------------------------------------
extern "C" void kernel_launch(void* const* d_in, const int* in_sizes, int n_in,
                              void* d_out, int out_size) {
    const float* x   = (const float*)d_in[0];  // (8, 64, 16384)
    const float* A   = (const float*)d_in[1];  // (256, 2)
    const float* Bm  = (const float*)d_in[2];  // (256, 64)
    const float* ldt = (const float*)d_in[3];  // (256,)
    const float* Cm  = (const float*)d_in[4];  // (64, 256)
    float* y = (float*)d_out;                  // (8, 64, 16384)

    cudaFuncSetAttribute(kC, cudaFuncAttributeMaxDynamicSharedMemorySize, SMEM_C);

    kP<<<1, 256>>>(A, Bm, ldt, Cm);
    kA<<<dim3(T_LEN / (SUB_A * NSUB), BATCH), 256>>>(x);
    kB<<<256, 256>>>();
    kC<<<dim3(T_LEN / TILE_C, BATCH), 256, SMEM_C>>>(y);
}

// round 11
// speedup vs baseline: 1.0359x; 1.0359x over previous
#include <cuda_runtime.h>
#include <math.h>
#include <stdint.h>

#define BATCH   8
#define CIN     64
#define COUT    64
#define NCO     256
#define T_LEN   16384
#define CHUNK   16
#define NCH     (T_LEN / CHUNK)      // 1024

// ---------------- scratch (device globals: no cudaMalloc allowed) ----------
__device__ float  g_u[(size_t)BATCH * NCO * T_LEN];   // u[b][n][t]
__device__ float2 g_lam[NCO];                         // lambda
__device__ float2 g_lamL[NCO];                        // lambda^16   (dbl-accurate)
__device__ float2 g_lamL32[NCO];                      // lambda^512  (dbl-accurate)
__device__ float  g_bh2[CIN * NCO * 2];               // B_hat dup pairs [c][n](w,w)
__device__ float  g_ct2[NCO * COUT * 2];              // C dup pairs [n][d](w,w)
__device__ float2 g_zend[(size_t)BATCH * NCO * NCH];
__device__ float2 g_zstart[(size_t)BATCH * NCO * NCH];

// ---------------- packed fp32x2 helpers (sm_100+) --------------------------
__device__ __forceinline__ void fma2(unsigned long long& acc,
                                     unsigned long long a, unsigned long long b) {
    asm("fma.rn.f32x2 %0, %1, %2, %0;" : "+l"(acc) : "l"(a), "l"(b));
}
__device__ __forceinline__ void cp16(uint32_t s, const float* g) {
    asm volatile("cp.async.cg.shared.global [%0], [%1], 16;\n"
                 :: "r"(s), "l"(g) : "memory");
}
__device__ __forceinline__ uint32_t smem_u32(const void* p) {
    uint32_t r;
    asm("{ .reg .u64 t0_; cvta.to.shared.u64 t0_, %1; cvt.u32.u64 %0, t0_; }"
        : "=r"(r) : "l"(p));
    return r;
}

// ---------------- kernel P: per-coefficient precompute ---------------------
__global__ void kP(const float* __restrict__ A, const float* __restrict__ Bm,
                   const float* __restrict__ log_dt, const float* __restrict__ Cm) {
    int n = threadIdx.x;              // 256 threads, one per coeff
    double la = (double)A[2 * n];
    double ai = (double)A[2 * n + 1];
    double dt = exp((double)log_dt[n]);
    double sp = log1p(exp(la));       // softplus
    double re = -dt * sp;
    double im =  dt * ai;
    double er = exp(re);
    g_lam[n]  = make_float2((float)(er * cos(im)), (float)(er * sin(im)));
    double erL = exp(re * (double)CHUNK);
    double imL = im * (double)CHUNK;
    g_lamL[n] = make_float2((float)(erL * cos(imL)), (float)(erL * sin(imL)));
    double er32 = exp(re * (double)(CHUNK * 32));
    double im32 = im * (double)(CHUNK * 32);
    g_lamL32[n] = make_float2((float)(er32 * cos(im32)), (float)(er32 * sin(im32)));
    float dtf = (float)dt;
    for (int c = 0; c < CIN; c++) {
        float w = Bm[n * CIN + c] * dtf;
        g_bh2[(c * NCO + n) * 2 + 0] = w;
        g_bh2[(c * NCO + n) * 2 + 1] = w;
    }
    for (int d = 0; d < COUT; d++) {
        float w = Cm[d * NCO + n];
        g_ct2[(n * COUT + d) * 2 + 0] = w;
        g_ct2[(n * COUT + d) * 2 + 1] = w;
    }
}

// ---------------- kernel A: u = B_hat @ x  (+ fused pass-1 scan) -----------
// CTA = (t-macro-tile 256, b), 256 threads, 4 sub-tiles of 64t. Deep cp.async
// pipeline: next sub-tile's DMA issued BEFORE waiting on the current one.
#define SUB_A  64
#define NSUB   4
#define XSP    68
#define XPANE  (CIN * XSP)                    // floats per x panel

__global__ void __launch_bounds__(256, 2) kA(const float* __restrict__ x) {
    __shared__ float xs[2 * XPANE];           // 34.8 KB
    int b = blockIdx.y, mt = blockIdx.x;
    int tid = threadIdx.x;
    size_t tbase = (size_t)mt * (SUB_A * NSUB);
    uint32_t sbase = smem_u32(xs);

    // prefetch sub-tile 0 into buffer 0 (64c x 64t = 1024 float4)
    for (int i = tid; i < CIN * 16; i += 256) {
        int c = i >> 4, q = i & 15;
        cp16(sbase + (uint32_t)(c * XSP + 4 * q) * 4,
             &x[((size_t)(b * CIN + c)) * T_LEN + tbase + 4 * q]);
    }
    asm volatile("cp.async.commit_group;\n" ::: "memory");

    int n0   = (tid >> 2) * 4;
    int tg   = tid & 3;
    int toff = tg * 16;

    for (int s = 0; s < NSUB; s++) {
        // issue next sub-tile's DMA first: overlaps the whole compute below
        if (s < NSUB - 1) {
            uint32_t nb = (uint32_t)(((s + 1) & 1) * XPANE) * 4;
            for (int i = tid; i < CIN * 16; i += 256) {
                int c = i >> 4, q = i & 15;
                cp16(sbase + nb + (uint32_t)(c * XSP + 4 * q) * 4,
                     &x[((size_t)(b * CIN + c)) * T_LEN + tbase + (s + 1) * SUB_A + 4 * q]);
            }
            asm volatile("cp.async.commit_group;\n" ::: "memory");
            asm volatile("cp.async.wait_group 1;\n" ::: "memory");
        } else {
            asm volatile("cp.async.wait_group 0;\n" ::: "memory");
        }
        __syncthreads();

        float* cur = xs + (s & 1) * XPANE;
        unsigned long long acc2[4][8];        // 4 n x 16 t
#pragma unroll
        for (int r = 0; r < 4; r++)
#pragma unroll
            for (int j = 0; j < 8; j++) acc2[r][j] = 0ULL;

        for (int c = 0; c < CIN; c++) {
            const ulonglong2* wv =
                (const ulonglong2*)&g_bh2[(c * NCO + n0) * 2];  // dup pairs
            ulonglong2 w01 = wv[0], w23 = wv[1];
            unsigned long long w[4] = {w01.x, w01.y, w23.x, w23.y};
            const ulonglong2* xv = (const ulonglong2*)&cur[c * XSP + toff];
            ulonglong2 va = xv[0], vb = xv[1], vc = xv[2], vd = xv[3];
            unsigned long long v[8] = {va.x, va.y, vb.x, vb.y,
                                       vc.x, vc.y, vd.x, vd.y};
#pragma unroll
            for (int r = 0; r < 4; r++)
#pragma unroll
                for (int j = 0; j < 8; j++)
                    fma2(acc2[r][j], w[r], v[j]);
        }

        // pass-1: 16-step chunk-local recurrence, zero init; store u
        size_t t0 = tbase + (size_t)s * SUB_A;
        int chunk = mt * 16 + s * 4 + tg;
#pragma unroll
        for (int r = 0; r < 4; r++) {
            int n = n0 + r;
            float2 lam = g_lam[n];
            float zr = 0.f, zi = 0.f;
#pragma unroll
            for (int j = 0; j < 8; j++) {
                float2 u2 = *(float2*)&acc2[r][j];
                float nr = fmaf(lam.x, zr, fmaf(-lam.y, zi, u2.x));
                float ni = fmaf(lam.x, zi, lam.y * zr);
                zr = nr; zi = ni;
                nr = fmaf(lam.x, zr, fmaf(-lam.y, zi, u2.y));
                ni = fmaf(lam.x, zi, lam.y * zr);
                zr = nr; zi = ni;
            }
            g_zend[((size_t)(b * NCO + n)) * NCH + chunk] = make_float2(zr, zi);

            float* orow = &g_u[((size_t)(b * NCO + n)) * T_LEN + t0 + toff];
#pragma unroll
            for (int q = 0; q < 4; q++)
                *(ulonglong2*)&orow[4 * q] =
                    make_ulonglong2(acc2[r][2 * q], acc2[r][2 * q + 1]);
        }
        __syncthreads();   // protect buffer (s&1) before iter s+1 overwrites it
    }
}

// ---------------- kernel B: cross-chunk scan, warp-parallel ----------------
// One warp per chain (2048 chains). Lane owns 32 contiguous chunk states:
// local total -> Kogge-Stone scan of affine maps (a,b) -> replay + write.
__global__ void __launch_bounds__(256) kB() {
    int warp = (blockIdx.x << 3) + (threadIdx.x >> 5);  // chain = b*256+n
    int lane = threadIdx.x & 31;
    int n = warp & 255;
    float2 lamL  = g_lamL[n];
    float2 lam32 = g_lamL32[n];
    size_t base = (size_t)warp * NCH + (size_t)lane * 32;

    float2 z[32];
#pragma unroll
    for (int i = 0; i < 32; i++) z[i] = g_zend[base + i];

    // segment total: state after 32 steps with zero init (complex input)
    float tr = 0.f, ti = 0.f;
#pragma unroll
    for (int i = 0; i < 32; i++) {
        float nr = fmaf(lamL.x, tr, fmaf(-lamL.y, ti, z[i].x));
        float ni = fmaf(lamL.x, ti, fmaf( lamL.y, tr, z[i].y));
        tr = nr; ti = ni;
    }

    // KS inclusive scan of affine maps f(s) = a*s + b, a = lamL^32 = lam32
    float ar = lam32.x, ai = lam32.y, br = tr, bi = ti;
#pragma unroll
    for (int d = 1; d < 32; d <<= 1) {
        float par = __shfl_up_sync(0xffffffffu, ar, d);
        float pai = __shfl_up_sync(0xffffffffu, ai, d);
        float pbr = __shfl_up_sync(0xffffffffu, br, d);
        float pbi = __shfl_up_sync(0xffffffffu, bi, d);
        if (lane >= d) {
            float nbr = fmaf(ar, pbr, fmaf(-ai, pbi, br));   // b = a*pb + b
            float nbi = fmaf(ar, pbi, fmaf( ai, pbr, bi));
            float nar = fmaf(ar, par, -ai * pai);            // a = a*pa
            float nai = fmaf(ar, pai,  ai * par);
            br = nbr; bi = nbi; ar = nar; ai = nai;
        }
    }
    // state entering this lane's segment = inclusive result of lane-1
    float er = __shfl_up_sync(0xffffffffu, br, 1);
    float ei = __shfl_up_sync(0xffffffffu, bi, 1);
    if (lane == 0) { er = 0.f; ei = 0.f; }

    // replay segment, writing the state entering each chunk
    float gr = er, gi = ei;
#pragma unroll
    for (int i = 0; i < 32; i++) {
        g_zstart[base + i] = make_float2(gr, gi);
        float nr = fmaf(lamL.x, gr, fmaf(-lamL.y, gi, z[i].x));
        float ni = fmaf(lamL.x, gi, fmaf( lamL.y, gr, z[i].y));
        gr = nr; gi = ni;
    }
}

// ---------------- kernel C: pass-2 replay + y = C @ v ----------------------
// CTA = (t-tile of 256, b), 256 threads. 8 n-panels of 32, deep cp.async
// pipeline (DMA of panel p+1 overlaps replay + GEMM of panel p).
#define TILE_C 256
#define NPC    32
#define UPP    260
#define PANE   (NPC * UPP)                    // floats per panel buffer
#define SMEM_C (2 * PANE * 4)                 // 66.6 KB

extern __shared__ float s_dyn[];

__global__ void __launch_bounds__(256, 2) kC(float* __restrict__ out) {
    int b = blockIdx.y, tile = blockIdx.x;
    int tid = threadIdx.x;
    size_t t0 = (size_t)tile * TILE_C;
    uint32_t sbase = smem_u32(s_dyn);

    int d0   = (tid & 15) * 4;
    int tgof = (tid >> 4) * 16;

    unsigned long long acc2[4][8];            // 4 d x 16 t
#pragma unroll
    for (int r = 0; r < 4; r++)
#pragma unroll
        for (int i = 0; i < 8; i++) acc2[r][i] = 0ULL;

    // prefetch panel 0 into buffer 0
    for (int i = tid; i < NPC * 64; i += 256) {
        int np = i >> 6, q = i & 63;
        cp16(sbase + (uint32_t)(np * UPP + 4 * q) * 4,
             &g_u[((size_t)(b * NCO + np)) * T_LEN + t0 + 4 * q]);
    }
    asm volatile("cp.async.commit_group;\n" ::: "memory");

    for (int p = 0; p < 8; p++) {
        // issue next panel's DMA first: overlaps replay + GEMM below
        if (p < 7) {
            uint32_t nb = (uint32_t)(((p + 1) & 1) * PANE) * 4;
            for (int i = tid; i < NPC * 64; i += 256) {
                int np = i >> 6, q = i & 63;
                cp16(sbase + nb + (uint32_t)(np * UPP + 4 * q) * 4,
                     &g_u[((size_t)(b * NCO + (p + 1) * NPC + np)) * T_LEN + t0 + 4 * q]);
            }
            asm volatile("cp.async.commit_group;\n" ::: "memory");
            asm volatile("cp.async.wait_group 1;\n" ::: "memory");
        } else {
            asm volatile("cp.async.wait_group 0;\n" ::: "memory");
        }
        __syncthreads();

        float* cur = s_dyn + (p & 1) * PANE;

        // pass-2 replay: 512 slots (32 n x 16 chunks of 16), 2 per thread
        for (int s = tid; s < NPC * 16; s += 256) {
            int n = s >> 4, c16 = s & 15;
            float2 lam = g_lam[p * NPC + n];
            float2 zs = g_zstart[((size_t)(b * NCO + p * NPC + n)) * NCH
                                 + tile * 16 + c16];
            float zr = zs.x, zi = zs.y;
            float* row = &cur[n * UPP + c16 * 16];
#pragma unroll
            for (int q = 0; q < 4; q++) {
                float4 uv = *(float4*)&row[4 * q];
                float nr, ni;
                nr = fmaf(lam.x, zr, fmaf(-lam.y, zi, uv.x));
                ni = fmaf(lam.x, zi, lam.y * zr); zr = nr; zi = ni; uv.x = zr;
                nr = fmaf(lam.x, zr, fmaf(-lam.y, zi, uv.y));
                ni = fmaf(lam.x, zi, lam.y * zr); zr = nr; zi = ni; uv.y = zr;
                nr = fmaf(lam.x, zr, fmaf(-lam.y, zi, uv.z));
                ni = fmaf(lam.x, zi, lam.y * zr); zr = nr; zi = ni; uv.z = zr;
                nr = fmaf(lam.x, zr, fmaf(-lam.y, zi, uv.w));
                ni = fmaf(lam.x, zi, lam.y * zr); zr = nr; zi = ni; uv.w = zr;
                *(float4*)&row[4 * q] = uv;
            }
        }
        __syncthreads();

        // GEMM: acc[d][t] += ct[n][d] * v[n][t]  (dup-pair weights, no movs)
        for (int nn = 0; nn < NPC; nn++) {
            const ulonglong2* wv =
                (const ulonglong2*)&g_ct2[((p * NPC + nn) * COUT + d0) * 2];
            ulonglong2 w01 = wv[0], w23 = wv[1];
            unsigned long long w[4] = {w01.x, w01.y, w23.x, w23.y};
            const ulonglong2* vv = (const ulonglong2*)&cur[nn * UPP + tgof];
            ulonglong2 v0 = vv[0], v1 = vv[1], v2 = vv[2], v3 = vv[3];
            unsigned long long v[8] = {v0.x, v0.y, v1.x, v1.y, v2.x, v2.y, v3.x, v3.y};
#pragma unroll
            for (int r = 0; r < 4; r++)
#pragma unroll
                for (int j = 0; j < 8; j++)
                    fma2(acc2[r][j], w[r], v[j]);
        }
        __syncthreads();   // protect buffer (p&1) before iter p+1 overwrites it
    }

    // write y: 4 rows of 16 consecutive floats each
#pragma unroll
    for (int r = 0; r < 4; r++) {
        float* orow = &out[((size_t)(b * COUT + d0 + r)) * T_LEN + t0 + tgof];
#pragma unroll
        for (int q = 0; q < 4; q++)
            *(ulonglong2*)&orow[4 * q] =
                make_ulonglong2(acc2[r][2 * q], acc2[r][2 * q + 1]);
    }
}

// ---------------- launch ----------------------------------------------------
extern "C" void kernel_launch(void* const* d_in, const int* in_sizes, int n_in,
                              void* d_out, int out_size) {
    const float* x   = (const float*)d_in[0];  // (8, 64, 16384)
    const float* A   = (const float*)d_in[1];  // (256, 2)
    const float* Bm  = (const float*)d_in[2];  // (256, 64)
    const float* ldt = (const float*)d_in[3];  // (256,)
    const float* Cm  = (const float*)d_in[4];  // (64, 256)
    float* y = (float*)d_out;                  // (8, 64, 16384)

    cudaFuncSetAttribute(kC, cudaFuncAttributeMaxDynamicSharedMemorySize, SMEM_C);

    kP<<<1, 256>>>(A, Bm, ldt, Cm);
    kA<<<dim3(T_LEN / (SUB_A * NSUB), BATCH), 256>>>(x);
    kB<<<256, 256>>>();
    kC<<<dim3(T_LEN / TILE_C, BATCH), 256, SMEM_C>>>(y);
}

// round 12
// speedup vs baseline: 1.1211x; 1.0823x over previous
#include <cuda_runtime.h>
#include <math.h>
#include <stdint.h>

#define BATCH   8
#define CIN     64
#define COUT    64
#define NCO     256
#define T_LEN   16384
#define CHUNK   16
#define NCH     (T_LEN / CHUNK)      // 1024

// ---------------- scratch (device globals: no cudaMalloc allowed) ----------
__device__ float  g_u[(size_t)BATCH * NCO * T_LEN];   // u[b][n][t]
__device__ float2 g_lam[NCO];                         // lambda
__device__ float2 g_lamL[NCO];                        // lambda^16   (dbl-accurate)
__device__ float2 g_lamL32[NCO];                      // lambda^512  (dbl-accurate)
__device__ float  g_bhT[CIN * NCO];                   // B_hat transposed [c][n]
__device__ float  g_ctT[NCO * COUT];                  // C transposed [n][d]
__device__ float2 g_zend[(size_t)BATCH * NCO * NCH];
__device__ float2 g_zstart[(size_t)BATCH * NCO * NCH];

// ---------------- packed fp32x2 helpers (sm_100+) --------------------------
__device__ __forceinline__ void fma2(unsigned long long& acc,
                                     unsigned long long a, unsigned long long b) {
    asm("fma.rn.f32x2 %0, %1, %2, %0;" : "+l"(acc) : "l"(a), "l"(b));
}
__device__ __forceinline__ unsigned long long bcast2(float w) {
    unsigned long long r;
    asm("mov.b64 %0, {%1, %1};" : "=l"(r) : "f"(w));
    return r;
}
__device__ __forceinline__ void cp16(uint32_t s, const float* g) {
    asm volatile("cp.async.cg.shared.global [%0], [%1], 16;\n"
                 :: "r"(s), "l"(g) : "memory");
}
__device__ __forceinline__ uint32_t smem_u32(const void* p) {
    uint32_t r;
    asm("{ .reg .u64 t0_; cvta.to.shared.u64 t0_, %1; cvt.u32.u64 %0, t0_; }"
        : "=r"(r) : "l"(p));
    return r;
}

// ---------------- kernel P: per-coefficient precompute ---------------------
__global__ void kP(const float* __restrict__ A, const float* __restrict__ Bm,
                   const float* __restrict__ log_dt, const float* __restrict__ Cm) {
    int n = threadIdx.x;              // 256 threads, one per coeff
    double la = (double)A[2 * n];
    double ai = (double)A[2 * n + 1];
    double dt = exp((double)log_dt[n]);
    double sp = log1p(exp(la));       // softplus
    double re = -dt * sp;
    double im =  dt * ai;
    double er = exp(re);
    g_lam[n]  = make_float2((float)(er * cos(im)), (float)(er * sin(im)));
    double erL = exp(re * (double)CHUNK);
    double imL = im * (double)CHUNK;
    g_lamL[n] = make_float2((float)(erL * cos(imL)), (float)(erL * sin(imL)));
    double er32 = exp(re * (double)(CHUNK * 32));
    double im32 = im * (double)(CHUNK * 32);
    g_lamL32[n] = make_float2((float)(er32 * cos(im32)), (float)(er32 * sin(im32)));
    float dtf = (float)dt;
    for (int c = 0; c < CIN; c++)
        g_bhT[c * NCO + n] = Bm[n * CIN + c] * dtf;
    for (int d = 0; d < COUT; d++)
        g_ctT[n * COUT + d] = Cm[d * NCO + n];
}

// ---------------- kernel A: u = B_hat @ x  (+ fused pass-1 scan) -----------
// CTA = (t-macro-tile 256, b), 256 threads, 4 sub-tiles of 64t, double-
// buffered cp.async x panels. Thread = 4n x 16t register tile.
// Weight LDG software-pipelined one iteration ahead.
#define SUB_A  64
#define NSUB   4
#define XSP    68
#define XPANE  (CIN * XSP)                    // floats per x panel

__global__ void __launch_bounds__(256, 2) kA(const float* __restrict__ x) {
    __shared__ float xs[2 * XPANE];           // 34.8 KB
    int b = blockIdx.y, mt = blockIdx.x;
    int tid = threadIdx.x;
    size_t tbase = (size_t)mt * (SUB_A * NSUB);
    uint32_t sbase = smem_u32(xs);

    // prefetch sub-tile 0 into buffer 0 (64c x 64t = 1024 float4)
    for (int i = tid; i < CIN * 16; i += 256) {
        int c = i >> 4, q = i & 15;
        cp16(sbase + (uint32_t)(c * XSP + 4 * q) * 4,
             &x[((size_t)(b * CIN + c)) * T_LEN + tbase + 4 * q]);
    }
    asm volatile("cp.async.commit_group;\n" ::: "memory");

    int n0   = (tid >> 2) * 4;
    int tg   = tid & 3;
    int toff = tg * 16;

    for (int s = 0; s < NSUB; s++) {
        float* cur = xs + (s & 1) * XPANE;
        asm volatile("cp.async.wait_group 0;\n" ::: "memory");
        __syncthreads();

        // prefetch next sub-tile into the other buffer; overlaps GEMM below
        if (s < NSUB - 1) {
            uint32_t nb = (uint32_t)(((s + 1) & 1) * XPANE) * 4;
            for (int i = tid; i < CIN * 16; i += 256) {
                int c = i >> 4, q = i & 15;
                cp16(sbase + nb + (uint32_t)(c * XSP + 4 * q) * 4,
                     &x[((size_t)(b * CIN + c)) * T_LEN + tbase + (s + 1) * SUB_A + 4 * q]);
            }
            asm volatile("cp.async.commit_group;\n" ::: "memory");
        }

        unsigned long long acc2[4][8];        // 4 n x 16 t
#pragma unroll
        for (int r = 0; r < 4; r++)
#pragma unroll
            for (int j = 0; j < 8; j++) acc2[r][j] = 0ULL;

        // software-pipelined weight load: LDG for c+1 issues before c's FMAs
        float4 wv = *(const float4*)&g_bhT[0 * NCO + n0];
#pragma unroll 2
        for (int c = 0; c < CIN; c++) {
            float4 wnext = (c < CIN - 1)
                ? *(const float4*)&g_bhT[(c + 1) * NCO + n0] : wv;
            unsigned long long w[4] = {bcast2(wv.x), bcast2(wv.y),
                                       bcast2(wv.z), bcast2(wv.w)};
            const ulonglong2* xv = (const ulonglong2*)&cur[c * XSP + toff];
            ulonglong2 va = xv[0], vb = xv[1], vc = xv[2], vd = xv[3];
            unsigned long long v[8] = {va.x, va.y, vb.x, vb.y,
                                       vc.x, vc.y, vd.x, vd.y};
#pragma unroll
            for (int r = 0; r < 4; r++)
#pragma unroll
                for (int j = 0; j < 8; j++)
                    fma2(acc2[r][j], w[r], v[j]);
            wv = wnext;
        }

        // pass-1: 16-step chunk-local recurrence, zero init; store u
        size_t t0 = tbase + (size_t)s * SUB_A;
        int chunk = mt * 16 + s * 4 + tg;
#pragma unroll
        for (int r = 0; r < 4; r++) {
            int n = n0 + r;
            float2 lam = g_lam[n];
            float zr = 0.f, zi = 0.f;
#pragma unroll
            for (int j = 0; j < 8; j++) {
                float2 u2 = *(float2*)&acc2[r][j];
                float nr = fmaf(lam.x, zr, fmaf(-lam.y, zi, u2.x));
                float ni = fmaf(lam.x, zi, lam.y * zr);
                zr = nr; zi = ni;
                nr = fmaf(lam.x, zr, fmaf(-lam.y, zi, u2.y));
                ni = fmaf(lam.x, zi, lam.y * zr);
                zr = nr; zi = ni;
            }
            g_zend[((size_t)(b * NCO + n)) * NCH + chunk] = make_float2(zr, zi);

            float* orow = &g_u[((size_t)(b * NCO + n)) * T_LEN + t0 + toff];
#pragma unroll
            for (int q = 0; q < 4; q++)
                *(ulonglong2*)&orow[4 * q] =
                    make_ulonglong2(acc2[r][2 * q], acc2[r][2 * q + 1]);
        }
    }
}

// ---------------- kernel B: cross-chunk scan, warp-parallel ----------------
// One warp per chain (2048 chains). Lane owns 32 contiguous chunk states:
// local total -> Kogge-Stone scan of affine maps (a,b) -> replay + write.
__global__ void __launch_bounds__(256) kB() {
    int warp = (blockIdx.x << 3) + (threadIdx.x >> 5);  // chain = b*256+n
    int lane = threadIdx.x & 31;
    int n = warp & 255;
    float2 lamL  = g_lamL[n];
    float2 lam32 = g_lamL32[n];
    size_t base = (size_t)warp * NCH + (size_t)lane * 32;

    float2 z[32];
#pragma unroll
    for (int i = 0; i < 32; i++) z[i] = g_zend[base + i];

    // segment total: state after 32 steps with zero init (complex input)
    float tr = 0.f, ti = 0.f;
#pragma unroll
    for (int i = 0; i < 32; i++) {
        float nr = fmaf(lamL.x, tr, fmaf(-lamL.y, ti, z[i].x));
        float ni = fmaf(lamL.x, ti, fmaf( lamL.y, tr, z[i].y));
        tr = nr; ti = ni;
    }

    // KS inclusive scan of affine maps f(s) = a*s + b, a = lamL^32 = lam32
    float ar = lam32.x, ai = lam32.y, br = tr, bi = ti;
#pragma unroll
    for (int d = 1; d < 32; d <<= 1) {
        float par = __shfl_up_sync(0xffffffffu, ar, d);
        float pai = __shfl_up_sync(0xffffffffu, ai, d);
        float pbr = __shfl_up_sync(0xffffffffu, br, d);
        float pbi = __shfl_up_sync(0xffffffffu, bi, d);
        if (lane >= d) {
            float nbr = fmaf(ar, pbr, fmaf(-ai, pbi, br));   // b = a*pb + b
            float nbi = fmaf(ar, pbi, fmaf( ai, pbr, bi));
            float nar = fmaf(ar, par, -ai * pai);            // a = a*pa
            float nai = fmaf(ar, pai,  ai * par);
            br = nbr; bi = nbi; ar = nar; ai = nai;
        }
    }
    // state entering this lane's segment = inclusive result of lane-1
    float er = __shfl_up_sync(0xffffffffu, br, 1);
    float ei = __shfl_up_sync(0xffffffffu, bi, 1);
    if (lane == 0) { er = 0.f; ei = 0.f; }

    // replay segment, writing the state entering each chunk
    float gr = er, gi = ei;
#pragma unroll
    for (int i = 0; i < 32; i++) {
        g_zstart[base + i] = make_float2(gr, gi);
        float nr = fmaf(lamL.x, gr, fmaf(-lamL.y, gi, z[i].x));
        float ni = fmaf(lamL.x, gi, fmaf( lamL.y, gr, z[i].y));
        gr = nr; gi = ni;
    }
}

// ---------------- kernel C: pass-2 replay + y = C @ v ----------------------
// CTA = (t-tile of 256, b), 256 threads. 8 n-panels of 32, double-buffered
// cp.async. Thread = 4d x 16t: d0 = (tid&15)*4, tg = tid>>4.
// Weight LDG software-pipelined one iteration ahead.
#define TILE_C 256
#define NPC    32
#define UPP    260
#define PANE   (NPC * UPP)                    // floats per panel buffer
#define SMEM_C (2 * PANE * 4)                 // 66.6 KB

extern __shared__ float s_dyn[];

__global__ void __launch_bounds__(256, 2) kC(float* __restrict__ out) {
    int b = blockIdx.y, tile = blockIdx.x;
    int tid = threadIdx.x;
    size_t t0 = (size_t)tile * TILE_C;
    uint32_t sbase = smem_u32(s_dyn);

    int d0   = (tid & 15) * 4;
    int tgof = (tid >> 4) * 16;

    unsigned long long acc2[4][8];            // 4 d x 16 t
#pragma unroll
    for (int r = 0; r < 4; r++)
#pragma unroll
        for (int i = 0; i < 8; i++) acc2[r][i] = 0ULL;

    // prefetch panel 0 into buffer 0
    for (int i = tid; i < NPC * 64; i += 256) {
        int np = i >> 6, q = i & 63;
        cp16(sbase + (uint32_t)(np * UPP + 4 * q) * 4,
             &g_u[((size_t)(b * NCO + np)) * T_LEN + t0 + 4 * q]);
    }
    asm volatile("cp.async.commit_group;\n" ::: "memory");

    for (int p = 0; p < 8; p++) {
        float* cur = s_dyn + (p & 1) * PANE;
        asm volatile("cp.async.wait_group 0;\n" ::: "memory");
        __syncthreads();

        // pass-2 replay: 512 slots (32 n x 16 chunks of 16), 2 per thread
        for (int s = tid; s < NPC * 16; s += 256) {
            int n = s >> 4, c16 = s & 15;
            float2 lam = g_lam[p * NPC + n];
            float2 zs = g_zstart[((size_t)(b * NCO + p * NPC + n)) * NCH
                                 + tile * 16 + c16];
            float zr = zs.x, zi = zs.y;
            float* row = &cur[n * UPP + c16 * 16];
#pragma unroll
            for (int q = 0; q < 4; q++) {
                float4 uv = *(float4*)&row[4 * q];
                float nr, ni;
                nr = fmaf(lam.x, zr, fmaf(-lam.y, zi, uv.x));
                ni = fmaf(lam.x, zi, lam.y * zr); zr = nr; zi = ni; uv.x = zr;
                nr = fmaf(lam.x, zr, fmaf(-lam.y, zi, uv.y));
                ni = fmaf(lam.x, zi, lam.y * zr); zr = nr; zi = ni; uv.y = zr;
                nr = fmaf(lam.x, zr, fmaf(-lam.y, zi, uv.z));
                ni = fmaf(lam.x, zi, lam.y * zr); zr = nr; zi = ni; uv.z = zr;
                nr = fmaf(lam.x, zr, fmaf(-lam.y, zi, uv.w));
                ni = fmaf(lam.x, zi, lam.y * zr); zr = nr; zi = ni; uv.w = zr;
                *(float4*)&row[4 * q] = uv;
            }
        }
        __syncthreads();

        // kick off next panel's async load; overlaps the GEMM below
        if (p < 7) {
            uint32_t nb = (uint32_t)(((p + 1) & 1) * PANE) * 4;
            for (int i = tid; i < NPC * 64; i += 256) {
                int np = i >> 6, q = i & 63;
                cp16(sbase + nb + (uint32_t)(np * UPP + 4 * q) * 4,
                     &g_u[((size_t)(b * NCO + (p + 1) * NPC + np)) * T_LEN + t0 + 4 * q]);
            }
            asm volatile("cp.async.commit_group;\n" ::: "memory");
        }

        // GEMM: acc[d][t] += ct[n][d] * v[n][t]; weight LDG pipelined ahead
        float4 cw = *(const float4*)&g_ctT[(p * NPC + 0) * COUT + d0];
#pragma unroll 2
        for (int nn = 0; nn < NPC; nn++) {
            float4 cnext = (nn < NPC - 1)
                ? *(const float4*)&g_ctT[(p * NPC + nn + 1) * COUT + d0] : cw;
            unsigned long long w[4] = {bcast2(cw.x), bcast2(cw.y),
                                       bcast2(cw.z), bcast2(cw.w)};
            const ulonglong2* vv = (const ulonglong2*)&cur[nn * UPP + tgof];
            ulonglong2 v0 = vv[0], v1 = vv[1], v2 = vv[2], v3 = vv[3];
            unsigned long long v[8] = {v0.x, v0.y, v1.x, v1.y, v2.x, v2.y, v3.x, v3.y};
#pragma unroll
            for (int r = 0; r < 4; r++)
#pragma unroll
                for (int j = 0; j < 8; j++)
                    fma2(acc2[r][j], w[r], v[j]);
            cw = cnext;
        }
        __syncthreads();
    }

    // write y: 4 rows of 16 consecutive floats each
#pragma unroll
    for (int r = 0; r < 4; r++) {
        float* orow = &out[((size_t)(b * COUT + d0 + r)) * T_LEN + t0 + tgof];
#pragma unroll
        for (int q = 0; q < 4; q++)
            *(ulonglong2*)&orow[4 * q] =
                make_ulonglong2(acc2[r][2 * q], acc2[r][2 * q + 1]);
    }
}

// ---------------- launch ----------------------------------------------------
extern "C" void kernel_launch(void* const* d_in, const int* in_sizes, int n_in,
                              void* d_out, int out_size) {
    const float* x   = (const float*)d_in[0];  // (8, 64, 16384)
    const float* A   = (const float*)d_in[1];  // (256, 2)
    const float* Bm  = (const float*)d_in[2];  // (256, 64)
    const float* ldt = (const float*)d_in[3];  // (256,)
    const float* Cm  = (const float*)d_in[4];  // (64, 256)
    float* y = (float*)d_out;                  // (8, 64, 16384)

    cudaFuncSetAttribute(kC, cudaFuncAttributeMaxDynamicSharedMemorySize, SMEM_C);

    kP<<<1, 256>>>(A, Bm, ldt, Cm);
    kA<<<dim3(T_LEN / (SUB_A * NSUB), BATCH), 256>>>(x);
    kB<<<256, 256>>>();
    kC<<<dim3(T_LEN / TILE_C, BATCH), 256, SMEM_C>>>(y);
}

// round 13
// speedup vs baseline: 1.2987x; 1.1584x over previous
#include <cuda_runtime.h>
#include <math.h>
#include <stdint.h>

#define BATCH   8
#define CIN     64
#define COUT    64
#define NCO     256
#define T_LEN   16384
#define CHUNK   16
#define NCH     (T_LEN / CHUNK)      // 1024

// ---------------- scratch (device globals: no cudaMalloc allowed) ----------
__device__ float  g_u[(size_t)BATCH * NCO * T_LEN];   // u[b][n][t]
__device__ float2 g_lam[NCO];                         // lambda
__device__ float2 g_lamL[NCO];                        // lambda^16   (dbl-accurate)
__device__ float2 g_lamL32[NCO];                      // lambda^512  (dbl-accurate)
__device__ float  g_bhT[CIN * NCO];                   // B_hat transposed [c][n]
__device__ float  g_ctT[NCO * COUT];                  // C transposed [n][d]
__device__ float2 g_zend[(size_t)BATCH * NCO * NCH];
__device__ float2 g_zstart[(size_t)BATCH * NCO * NCH];

// ---------------- packed fp32x2 helpers (sm_100+) --------------------------
__device__ __forceinline__ void fma2(unsigned long long& acc,
                                     unsigned long long a, unsigned long long b) {
    asm("fma.rn.f32x2 %0, %1, %2, %0;" : "+l"(acc) : "l"(a), "l"(b));
}
__device__ __forceinline__ unsigned long long bcast2(float w) {
    unsigned long long r;
    asm("mov.b64 %0, {%1, %1};" : "=l"(r) : "f"(w));
    return r;
}
__device__ __forceinline__ void cp16(uint32_t s, const float* g) {
    asm volatile("cp.async.cg.shared.global [%0], [%1], 16;\n"
                 :: "r"(s), "l"(g) : "memory");
}
__device__ __forceinline__ uint32_t smem_u32(const void* p) {
    uint32_t r;
    asm("{ .reg .u64 t0_; cvta.to.shared.u64 t0_, %1; cvt.u32.u64 %0, t0_; }"
        : "=r"(r) : "l"(p));
    return r;
}

// ---------------- kernel P: per-coefficient precompute ---------------------
__global__ void kP(const float* __restrict__ A, const float* __restrict__ Bm,
                   const float* __restrict__ log_dt, const float* __restrict__ Cm) {
    int n = threadIdx.x;              // 256 threads, one per coeff
    double la = (double)A[2 * n];
    double ai = (double)A[2 * n + 1];
    double dt = exp((double)log_dt[n]);
    double sp = log1p(exp(la));       // softplus
    double re = -dt * sp;
    double im =  dt * ai;
    double er = exp(re);
    g_lam[n]  = make_float2((float)(er * cos(im)), (float)(er * sin(im)));
    double erL = exp(re * (double)CHUNK);
    double imL = im * (double)CHUNK;
    g_lamL[n] = make_float2((float)(erL * cos(imL)), (float)(erL * sin(imL)));
    double er32 = exp(re * (double)(CHUNK * 32));
    double im32 = im * (double)(CHUNK * 32);
    g_lamL32[n] = make_float2((float)(er32 * cos(im32)), (float)(er32 * sin(im32)));
    float dtf = (float)dt;
    for (int c = 0; c < CIN; c++)
        g_bhT[c * NCO + n] = Bm[n * CIN + c] * dtf;
    for (int d = 0; d < COUT; d++)
        g_ctT[n * COUT + d] = Cm[d * NCO + n];
}

// ---------------- kernel A: u = B_hat @ x  (+ fused pass-1 scan) -----------
// CTA = (t-macro-tile 256, b), 256 threads, 4 sub-tiles of 64t, double-
// buffered cp.async x panels. Thread = 4n x 16t register tile.  (R9 exact)
#define SUB_A  64
#define NSUB   4
#define XSP    68
#define XPANE  (CIN * XSP)                    // floats per x panel

__global__ void __launch_bounds__(256, 2) kA(const float* __restrict__ x) {
    __shared__ float xs[2 * XPANE];           // 34.8 KB
    int b = blockIdx.y, mt = blockIdx.x;
    int tid = threadIdx.x;
    size_t tbase = (size_t)mt * (SUB_A * NSUB);
    uint32_t sbase = smem_u32(xs);

    // prefetch sub-tile 0 into buffer 0 (64c x 64t = 1024 float4)
    for (int i = tid; i < CIN * 16; i += 256) {
        int c = i >> 4, q = i & 15;
        cp16(sbase + (uint32_t)(c * XSP + 4 * q) * 4,
             &x[((size_t)(b * CIN + c)) * T_LEN + tbase + 4 * q]);
    }
    asm volatile("cp.async.commit_group;\n" ::: "memory");

    int n0   = (tid >> 2) * 4;
    int tg   = tid & 3;
    int toff = tg * 16;

    for (int s = 0; s < NSUB; s++) {
        float* cur = xs + (s & 1) * XPANE;
        asm volatile("cp.async.wait_group 0;\n" ::: "memory");
        __syncthreads();

        // prefetch next sub-tile into the other buffer; overlaps GEMM below
        if (s < NSUB - 1) {
            uint32_t nb = (uint32_t)(((s + 1) & 1) * XPANE) * 4;
            for (int i = tid; i < CIN * 16; i += 256) {
                int c = i >> 4, q = i & 15;
                cp16(sbase + nb + (uint32_t)(c * XSP + 4 * q) * 4,
                     &x[((size_t)(b * CIN + c)) * T_LEN + tbase + (s + 1) * SUB_A + 4 * q]);
            }
            asm volatile("cp.async.commit_group;\n" ::: "memory");
        }

        unsigned long long acc2[4][8];        // 4 n x 16 t
#pragma unroll
        for (int r = 0; r < 4; r++)
#pragma unroll
            for (int j = 0; j < 8; j++) acc2[r][j] = 0ULL;

        for (int c = 0; c < CIN; c++) {
            float4 wv = *(const float4*)&g_bhT[c * NCO + n0];  // 128B/warp, L1
            unsigned long long w[4] = {bcast2(wv.x), bcast2(wv.y),
                                       bcast2(wv.z), bcast2(wv.w)};
            const ulonglong2* xv = (const ulonglong2*)&cur[c * XSP + toff];
            ulonglong2 va = xv[0], vb = xv[1], vc = xv[2], vd = xv[3];
            unsigned long long v[8] = {va.x, va.y, vb.x, vb.y,
                                       vc.x, vc.y, vd.x, vd.y};
#pragma unroll
            for (int r = 0; r < 4; r++)
#pragma unroll
                for (int j = 0; j < 8; j++)
                    fma2(acc2[r][j], w[r], v[j]);
        }

        // pass-1: 16-step chunk-local recurrence, zero init; store u
        size_t t0 = tbase + (size_t)s * SUB_A;
        int chunk = mt * 16 + s * 4 + tg;
#pragma unroll
        for (int r = 0; r < 4; r++) {
            int n = n0 + r;
            float2 lam = g_lam[n];
            float zr = 0.f, zi = 0.f;
#pragma unroll
            for (int j = 0; j < 8; j++) {
                float2 u2 = *(float2*)&acc2[r][j];
                float nr = fmaf(lam.x, zr, fmaf(-lam.y, zi, u2.x));
                float ni = fmaf(lam.x, zi, lam.y * zr);
                zr = nr; zi = ni;
                nr = fmaf(lam.x, zr, fmaf(-lam.y, zi, u2.y));
                ni = fmaf(lam.x, zi, lam.y * zr);
                zr = nr; zi = ni;
            }
            g_zend[((size_t)(b * NCO + n)) * NCH + chunk] = make_float2(zr, zi);

            float* orow = &g_u[((size_t)(b * NCO + n)) * T_LEN + t0 + toff];
#pragma unroll
            for (int q = 0; q < 4; q++)
                *(ulonglong2*)&orow[4 * q] =
                    make_ulonglong2(acc2[r][2 * q], acc2[r][2 * q + 1]);
        }
    }
}

// ---------------- kernel B: cross-chunk scan, smem-staged coalesced --------
// One warp per chain. Gmem traffic fully coalesced via padded smem transpose;
// per-lane segments then read/written from smem. Scan math identical to R9.
#define KB_W 4

__global__ void __launch_bounds__(128) kB() {
    __shared__ float2 st[KB_W][32 * 33];      // 33.8 KB, pad 33 vs bank conflicts
    int wid = threadIdx.x >> 5, lane = threadIdx.x & 31;
    int chain = blockIdx.x * KB_W + wid;      // chain = b*256 + n  (0..2047)
    int n = chain & 255;
    float2 lamL  = g_lamL[n];
    float2 lam32 = g_lamL32[n];
    size_t gbase = (size_t)chain * NCH;
    float2* s = st[wid];

    // coalesced load: iteration k, lane l <-> chunk k*32+l (256B/instr)
#pragma unroll
    for (int k = 0; k < 32; k++)
        s[k * 33 + lane] = g_zend[gbase + k * 32 + lane];
    __syncwarp();

    // lane's contiguous 32-chunk segment -> regs
    float2 z[32];
#pragma unroll
    for (int i = 0; i < 32; i++) z[i] = s[lane * 33 + i];

    // segment total: state after 32 steps with zero init
    float tr = 0.f, ti = 0.f;
#pragma unroll
    for (int i = 0; i < 32; i++) {
        float nr = fmaf(lamL.x, tr, fmaf(-lamL.y, ti, z[i].x));
        float ni = fmaf(lamL.x, ti, fmaf( lamL.y, tr, z[i].y));
        tr = nr; ti = ni;
    }

    // KS inclusive scan of affine maps f(s) = a*s + b, a = lamL^32 = lam32
    float ar = lam32.x, ai = lam32.y, br = tr, bi = ti;
#pragma unroll
    for (int d = 1; d < 32; d <<= 1) {
        float par = __shfl_up_sync(0xffffffffu, ar, d);
        float pai = __shfl_up_sync(0xffffffffu, ai, d);
        float pbr = __shfl_up_sync(0xffffffffu, br, d);
        float pbi = __shfl_up_sync(0xffffffffu, bi, d);
        if (lane >= d) {
            float nbr = fmaf(ar, pbr, fmaf(-ai, pbi, br));   // b = a*pb + b
            float nbi = fmaf(ar, pbi, fmaf( ai, pbr, bi));
            float nar = fmaf(ar, par, -ai * pai);            // a = a*pa
            float nai = fmaf(ar, pai,  ai * par);
            br = nbr; bi = nbi; ar = nar; ai = nai;
        }
    }
    // state entering this lane's segment = inclusive result of lane-1
    float er = __shfl_up_sync(0xffffffffu, br, 1);
    float ei = __shfl_up_sync(0xffffffffu, bi, 1);
    if (lane == 0) { er = 0.f; ei = 0.f; }

    // replay into smem (own slots), then coalesced store
    float gr = er, gi = ei;
#pragma unroll
    for (int i = 0; i < 32; i++) {
        s[lane * 33 + i] = make_float2(gr, gi);
        float nr = fmaf(lamL.x, gr, fmaf(-lamL.y, gi, z[i].x));
        float ni = fmaf(lamL.x, gi, fmaf( lamL.y, gr, z[i].y));
        gr = nr; gi = ni;
    }
    __syncwarp();
#pragma unroll
    for (int k = 0; k < 32; k++)
        g_zstart[gbase + k * 32 + lane] = s[k * 33 + lane];
}

// ---------------- kernel C: pass-2 replay + y = C @ v ----------------------
// CTA = (t-tile of 256, b), 256 threads. 8 n-panels of 32, double-buffered
// cp.async. Thread = 4d x 16t.  (R9 exact — measured-best shape)
#define TILE_C 256
#define NPC    32
#define UPP    260
#define PANE   (NPC * UPP)                    // floats per panel buffer
#define SMEM_C (2 * PANE * 4)                 // 66.6 KB

extern __shared__ float s_dyn[];

__global__ void __launch_bounds__(256, 2) kC(float* __restrict__ out) {
    int b = blockIdx.y, tile = blockIdx.x;
    int tid = threadIdx.x;
    size_t t0 = (size_t)tile * TILE_C;
    uint32_t sbase = smem_u32(s_dyn);

    int d0   = (tid & 15) * 4;
    int tgof = (tid >> 4) * 16;

    unsigned long long acc2[4][8];            // 4 d x 16 t
#pragma unroll
    for (int r = 0; r < 4; r++)
#pragma unroll
        for (int i = 0; i < 8; i++) acc2[r][i] = 0ULL;

    // prefetch panel 0 into buffer 0
    for (int i = tid; i < NPC * 64; i += 256) {
        int np = i >> 6, q = i & 63;
        cp16(sbase + (uint32_t)(np * UPP + 4 * q) * 4,
             &g_u[((size_t)(b * NCO + np)) * T_LEN + t0 + 4 * q]);
    }
    asm volatile("cp.async.commit_group;\n" ::: "memory");

    for (int p = 0; p < 8; p++) {
        float* cur = s_dyn + (p & 1) * PANE;
        asm volatile("cp.async.wait_group 0;\n" ::: "memory");
        __syncthreads();

        // pass-2 replay: 512 slots (32 n x 16 chunks of 16), 2 per thread
        for (int s = tid; s < NPC * 16; s += 256) {
            int n = s >> 4, c16 = s & 15;
            float2 lam = g_lam[p * NPC + n];
            float2 zs = g_zstart[((size_t)(b * NCO + p * NPC + n)) * NCH
                                 + tile * 16 + c16];
            float zr = zs.x, zi = zs.y;
            float* row = &cur[n * UPP + c16 * 16];
#pragma unroll
            for (int q = 0; q < 4; q++) {
                float4 uv = *(float4*)&row[4 * q];
                float nr, ni;
                nr = fmaf(lam.x, zr, fmaf(-lam.y, zi, uv.x));
                ni = fmaf(lam.x, zi, lam.y * zr); zr = nr; zi = ni; uv.x = zr;
                nr = fmaf(lam.x, zr, fmaf(-lam.y, zi, uv.y));
                ni = fmaf(lam.x, zi, lam.y * zr); zr = nr; zi = ni; uv.y = zr;
                nr = fmaf(lam.x, zr, fmaf(-lam.y, zi, uv.z));
                ni = fmaf(lam.x, zi, lam.y * zr); zr = nr; zi = ni; uv.z = zr;
                nr = fmaf(lam.x, zr, fmaf(-lam.y, zi, uv.w));
                ni = fmaf(lam.x, zi, lam.y * zr); zr = nr; zi = ni; uv.w = zr;
                *(float4*)&row[4 * q] = uv;
            }
        }
        __syncthreads();

        // kick off next panel's async load; overlaps the GEMM below
        if (p < 7) {
            uint32_t nb = (uint32_t)(((p + 1) & 1) * PANE) * 4;
            for (int i = tid; i < NPC * 64; i += 256) {
                int np = i >> 6, q = i & 63;
                cp16(sbase + nb + (uint32_t)(np * UPP + 4 * q) * 4,
                     &g_u[((size_t)(b * NCO + (p + 1) * NPC + np)) * T_LEN + t0 + 4 * q]);
            }
            asm volatile("cp.async.commit_group;\n" ::: "memory");
        }

        // GEMM: acc[d][t] += ct[n][d] * v[n][t]
        for (int nn = 0; nn < NPC; nn++) {
            float4 cw = *(const float4*)&g_ctT[(p * NPC + nn) * COUT + d0];
            unsigned long long w[4] = {bcast2(cw.x), bcast2(cw.y),
                                       bcast2(cw.z), bcast2(cw.w)};
            const ulonglong2* vv = (const ulonglong2*)&cur[nn * UPP + tgof];
            ulonglong2 v0 = vv[0], v1 = vv[1], v2 = vv[2], v3 = vv[3];
            unsigned long long v[8] = {v0.x, v0.y, v1.x, v1.y, v2.x, v2.y, v3.x, v3.y};
#pragma unroll
            for (int r = 0; r < 4; r++)
#pragma unroll
                for (int j = 0; j < 8; j++)
                    fma2(acc2[r][j], w[r], v[j]);
        }
        __syncthreads();
    }

    // write y: 4 rows of 16 consecutive floats each
#pragma unroll
    for (int r = 0; r < 4; r++) {
        float* orow = &out[((size_t)(b * COUT + d0 + r)) * T_LEN + t0 + tgof];
#pragma unroll
        for (int q = 0; q < 4; q++)
            *(ulonglong2*)&orow[4 * q] =
                make_ulonglong2(acc2[r][2 * q], acc2[r][2 * q + 1]);
    }
}

// ---------------- launch ----------------------------------------------------
extern "C" void kernel_launch(void* const* d_in, const int* in_sizes, int n_in,
                              void* d_out, int out_size) {
    const float* x   = (const float*)d_in[0];  // (8, 64, 16384)
    const float* A   = (const float*)d_in[1];  // (256, 2)
    const float* Bm  = (const float*)d_in[2];  // (256, 64)
    const float* ldt = (const float*)d_in[3];  // (256,)
    const float* Cm  = (const float*)d_in[4];  // (64, 256)
    float* y = (float*)d_out;                  // (8, 64, 16384)

    cudaFuncSetAttribute(kC, cudaFuncAttributeMaxDynamicSharedMemorySize, SMEM_C);

    kP<<<1, 256>>>(A, Bm, ldt, Cm);
    kA<<<dim3(T_LEN / (SUB_A * NSUB), BATCH), 256>>>(x);
    kB<<<512, 128>>>();
    kC<<<dim3(T_LEN / TILE_C, BATCH), 256, SMEM_C>>>(y);
}